// round 1
// baseline (speedup 1.0000x reference)
#include <cuda_runtime.h>
#include <cstdint>

// Problem constants
#define Bn 32
#define Ln 256
#define Dn 256
#define Hn 256
#define En 8
#define NLn 4
#define Kc 4                 // conv kernel width
#define BEn (Bn*En)          // 256
#define MROWS (Bn*En*Ln)     // 65536

// Scratch (device globals - no allocation allowed)
__device__ float g_ln[Bn*Ln*Dn];                 // 8 MB
__device__ float g_u[Bn*Ln*Dn];                  // 8 MB
__device__ float g_y[(size_t)Bn*En*Ln*Hn];       // 64 MB
__device__ float g_pre[(size_t)Bn*En*Ln*Hn];     // 64 MB

// ---------------------------------------------------------------------------
// LayerNorm: one block per token (B*L blocks, 256 threads)
// ---------------------------------------------------------------------------
__global__ void ln_kernel(const float* __restrict__ x, const float* __restrict__ g,
                          const float* __restrict__ bb, float* __restrict__ out)
{
    int token = blockIdx.x;
    int t = threadIdx.x;
    __shared__ float red[8];
    __shared__ float meanv, rstdv;

    float v = x[(size_t)token * Dn + t];

    float s = v;
    #pragma unroll
    for (int o = 16; o > 0; o >>= 1) s += __shfl_xor_sync(0xffffffffu, s, o);
    if ((t & 31) == 0) red[t >> 5] = s;
    __syncthreads();
    if (t == 0) {
        float m = 0.f;
        #pragma unroll
        for (int i = 0; i < 8; i++) m += red[i];
        meanv = m * (1.0f / Dn);
    }
    __syncthreads();

    float d = v - meanv;
    float sq = d * d;
    #pragma unroll
    for (int o = 16; o > 0; o >>= 1) sq += __shfl_xor_sync(0xffffffffu, sq, o);
    if ((t & 31) == 0) red[t >> 5] = sq;
    __syncthreads();
    if (t == 0) {
        float vv = 0.f;
        #pragma unroll
        for (int i = 0; i < 8; i++) vv += red[i];
        rstdv = rsqrtf(vv * (1.0f / Dn) + 1e-5f);
    }
    __syncthreads();

    out[(size_t)token * Dn + t] = d * rstdv * g[t] + bb[t];
}

// ---------------------------------------------------------------------------
// Depthwise causal conv1d (K=4, left pad 3) + bias
// ---------------------------------------------------------------------------
__global__ void conv_kernel(const float* __restrict__ ln, const float* __restrict__ cw,
                            const float* __restrict__ cb, float* __restrict__ u)
{
    int idx = blockIdx.x * 256 + threadIdx.x;     // B*L*D elements
    int d  = idx & 255;
    int l  = (idx >> 8) & 255;
    int b0 = idx >> 16;
    float acc = cb[d];
    #pragma unroll
    for (int j = 0; j < Kc; j++) {
        int ls = l - (Kc - 1) + j;
        if (ls >= 0)
            acc += ln[((size_t)b0 * Ln + ls) * Dn + d] * cw[d * Kc + j];
    }
    u[idx] = acc;
}

// ---------------------------------------------------------------------------
// Input GEMM: pre[row][h] = sum_f (in[row][f] * r[e][f]) * Wih[h][f], then
//             pre = pre * s[e][h] + bias[h].
// row = (b*E + e)*L + l ; layer0 reads u[b*L + l] (broadcast over e).
// Tile: 128(M) x 64(N), K-chunk 16, 256 threads, 8x4 microtile.
// ---------------------------------------------------------------------------
__global__ __launch_bounds__(256, 2)
void gemm_kernel(const float* __restrict__ inx, const float* __restrict__ Wih,
                 const float* __restrict__ rv, const float* __restrict__ sv,
                 const float* __restrict__ bv, float* __restrict__ pre, int layer0)
{
    __shared__ float As[16][128];
    __shared__ float Bs[16][64];

    int tid = threadIdx.x;
    int bm = blockIdx.x;      // 512
    int bn = blockIdx.y;      // 4

    // A-load mapping: 2 threads per row, 2 float4 each (16 K values per row)
    int lrA = tid >> 1;               // 0..127
    int kqA = (tid & 1) * 8;          // 0 or 8
    int rowA = bm * 128 + lrA;
    int eA = (rowA >> 8) & 7;         // (row / L) % E
    size_t srcRow;
    if (layer0) {
        int b0 = rowA >> 11;          // row / (E*L)
        int l  = rowA & 255;
        srcRow = (size_t)b0 * Ln + l;
    } else {
        srcRow = (size_t)rowA;
    }
    const float* arow = inx + srcRow * 256;
    const float* rrow = rv + (size_t)eA * 256;

    // B-load mapping: 4 threads per row (64 rows), 1 float4 each
    int nB = tid >> 2;                // 0..63
    int kqB = (tid & 3) * 4;
    const float* brow = Wih + (size_t)(bn * 64 + nB) * 256;

    int tn = (tid & 15) * 4;          // 0..60
    int tm = (tid >> 4) * 8;          // 0..120

    float acc[8][4];
    #pragma unroll
    for (int i = 0; i < 8; i++)
        #pragma unroll
        for (int j = 0; j < 4; j++) acc[i][j] = 0.f;

    for (int k0 = 0; k0 < 256; k0 += 16) {
        #pragma unroll
        for (int h8 = 0; h8 < 2; h8++) {
            float4 av = *(const float4*)(arow + k0 + kqA + h8 * 4);
            float4 rv4 = *(const float4*)(rrow + k0 + kqA + h8 * 4);
            av.x *= rv4.x; av.y *= rv4.y; av.z *= rv4.z; av.w *= rv4.w;
            As[kqA + h8 * 4 + 0][lrA] = av.x;
            As[kqA + h8 * 4 + 1][lrA] = av.y;
            As[kqA + h8 * 4 + 2][lrA] = av.z;
            As[kqA + h8 * 4 + 3][lrA] = av.w;
        }
        float4 bv4 = *(const float4*)(brow + k0 + kqB);
        Bs[kqB + 0][nB] = bv4.x;
        Bs[kqB + 1][nB] = bv4.y;
        Bs[kqB + 2][nB] = bv4.z;
        Bs[kqB + 3][nB] = bv4.w;
        __syncthreads();

        #pragma unroll
        for (int kk = 0; kk < 16; kk++) {
            float a0[8], b0r[4];
            *(float4*)&a0[0] = *(const float4*)&As[kk][tm];
            *(float4*)&a0[4] = *(const float4*)&As[kk][tm + 4];
            *(float4*)&b0r[0] = *(const float4*)&Bs[kk][tn];
            #pragma unroll
            for (int i = 0; i < 8; i++)
                #pragma unroll
                for (int j = 0; j < 4; j++)
                    acc[i][j] += a0[i] * b0r[j];
        }
        __syncthreads();
    }

    // epilogue: e is constant per block (128-row tile inside one (b,e) group of 256)
    int eE = ((bm * 128) >> 8) & 7;
    const float* srow = sv + (size_t)eE * 256 + bn * 64;
    const float* brow2 = bv + bn * 64;
    #pragma unroll
    for (int i = 0; i < 8; i++) {
        size_t row = (size_t)bm * 128 + tm + i;
        float* prow = pre + row * 256 + bn * 64;
        #pragma unroll
        for (int j = 0; j < 4; j++) {
            int h = tn + j;
            prow[h] = acc[i][j] * srow[h] + brow2[h];
        }
    }
}

// ---------------------------------------------------------------------------
// Recurrence: h_t = tanh(pre_t + W_hh @ h_{t-1}), per (b,e) independent.
// 64 clusters x 2 CTAs. Cluster c owns batch rows [4c, 4c+4).
// CTA rank q owns output rows k in [q*128, q*128+128), W half in REGISTERS
// (thread (tx,tz): W[q*128 + tx*4 + a][tz*32 + j], a<4, j<32 -> 128 regs).
// K-split across 8 warps; partials reduced via smem; new h exchanged with the
// peer CTA via DSMEM; one cluster barrier per step.
// ---------------------------------------------------------------------------
__device__ __forceinline__ uint32_t s2u(const void* p)
{
    uint32_t a;
    asm("{ .reg .u64 t; cvta.to.shared.u64 t, %1; cvt.u32.u64 %0, t; }"
        : "=r"(a) : "l"(p));
    return a;
}

__device__ __forceinline__ void cluster_sync_()
{
    asm volatile("barrier.cluster.arrive.aligned;\n\t"
                 "barrier.cluster.wait.aligned;" ::: "memory");
}

__global__ __launch_bounds__(256, 1) __cluster_dims__(2, 1, 1)
void rec_kernel(const float* __restrict__ pre, const float* __restrict__ Whh,
                float* __restrict__ yout, float* __restrict__ hlast)
{
    int q = blockIdx.x;        // cluster rank 0/1
    int c = blockIdx.y;        // cluster id 0..63
    int tid = threadIdx.x;
    int tz = tid >> 5;         // warp -> j slice [tz*32, tz*32+32)
    int tx = tid & 31;         // k tile -> rows tx*4 .. tx*4+3 (local)

    // W half in registers (loaded once)
    float w[4][32];
    #pragma unroll
    for (int a = 0; a < 4; a++) {
        const float* wr = Whh + (size_t)(q * 128 + tx * 4 + a) * Hn + tz * 32;
        #pragma unroll
        for (int j4 = 0; j4 < 8; j4++) {
            float4 v = *(const float4*)(wr + j4 * 4);
            w[a][j4 * 4 + 0] = v.x;
            w[a][j4 * 4 + 1] = v.y;
            w[a][j4 * 4 + 2] = v.z;
            w[a][j4 * 4 + 3] = v.w;
        }
    }

    __shared__ float hbuf[2][4][256];    // [parity][m][h]
    __shared__ float part[32][128];      // [tz*4+m][k_local]

    // init h0 = 0 (parity 0)
    for (int i = tid; i < 4 * 256; i += 256) ((float*)hbuf[0])[i] = 0.f;
    __syncthreads();
    cluster_sync_();

    // reduction-phase mapping: thread handles 2 outputs (same k, batch m0/m1)
    int rk = tid & 127;
    int mh = tid >> 7;         // 0/1
    int m0 = mh * 2, m1 = mh * 2 + 1;
    int kg = q * 128 + rk;     // global output index
    size_t be0 = (size_t)c * 4;

    // precompute peer DSMEM addresses for both parities
    uint32_t pa0[2], pa1[2];
    #pragma unroll
    for (int p = 0; p < 2; p++) {
        uint32_t a0 = s2u(&hbuf[p][m0][kg]);
        uint32_t a1 = s2u(&hbuf[p][m1][kg]);
        asm("mapa.shared::cluster.u32 %0, %1, %2;" : "=r"(pa0[p]) : "r"(a0), "r"(q ^ 1));
        asm("mapa.shared::cluster.u32 %0, %1, %2;" : "=r"(pa1[p]) : "r"(a1), "r"(q ^ 1));
    }

    int pq = 0;
    for (int t = 0; t < Ln; t++) {
        // prefetch pre for this step's two outputs (consumed after compute)
        float pv0 = pre[((be0 + m0) * Ln + t) * Hn + kg];
        float pv1 = pre[((be0 + m1) * Ln + t) * Hn + kg];

        // partial matvec over this warp's j slice
        float acc[4][4];
        #pragma unroll
        for (int m = 0; m < 4; m++)
            #pragma unroll
            for (int a = 0; a < 4; a++) acc[m][a] = 0.f;

        #pragma unroll
        for (int j4 = 0; j4 < 8; j4++) {
            float4 h0 = *(const float4*)&hbuf[pq][0][tz * 32 + j4 * 4];
            float4 h1 = *(const float4*)&hbuf[pq][1][tz * 32 + j4 * 4];
            float4 h2 = *(const float4*)&hbuf[pq][2][tz * 32 + j4 * 4];
            float4 h3 = *(const float4*)&hbuf[pq][3][tz * 32 + j4 * 4];
            float hv0[4] = {h0.x, h0.y, h0.z, h0.w};
            float hv1[4] = {h1.x, h1.y, h1.z, h1.w};
            float hv2[4] = {h2.x, h2.y, h2.z, h2.w};
            float hv3[4] = {h3.x, h3.y, h3.z, h3.w};
            #pragma unroll
            for (int jj = 0; jj < 4; jj++) {
                int j = j4 * 4 + jj;
                #pragma unroll
                for (int a = 0; a < 4; a++) {
                    acc[0][a] += w[a][j] * hv0[jj];
                    acc[1][a] += w[a][j] * hv1[jj];
                    acc[2][a] += w[a][j] * hv2[jj];
                    acc[3][a] += w[a][j] * hv3[jj];
                }
            }
        }
        #pragma unroll
        for (int m = 0; m < 4; m++)
            *(float4*)&part[tz * 4 + m][tx * 4] =
                make_float4(acc[m][0], acc[m][1], acc[m][2], acc[m][3]);
        __syncthreads();

        // reduce 8 K-slices, add pre, tanh
        float s0 = pv0, s1 = pv1;
        #pragma unroll
        for (int z = 0; z < 8; z++) {
            s0 += part[z * 4 + m0][rk];
            s1 += part[z * 4 + m1][rk];
        }
        float h0n = tanhf(s0);
        float h1n = tanhf(s1);

        yout[((be0 + m0) * Ln + t) * Hn + kg] = h0n;
        yout[((be0 + m1) * Ln + t) * Hn + kg] = h1n;

        int np = pq ^ 1;
        hbuf[np][m0][kg] = h0n;
        hbuf[np][m1][kg] = h1n;
        asm volatile("st.shared::cluster.f32 [%0], %1;" :: "r"(pa0[np]), "f"(h0n));
        asm volatile("st.shared::cluster.f32 [%0], %1;" :: "r"(pa1[np]), "f"(h1n));

        if (hlast != nullptr && t == Ln - 1) {
            hlast[(be0 + m0) * Hn + kg] = h0n;
            hlast[(be0 + m1) * Hn + kg] = h1n;
        }

        cluster_sync_();
        pq = np;
    }
}

// ---------------------------------------------------------------------------
// Launch
// ---------------------------------------------------------------------------
extern "C" void kernel_launch(void* const* d_in, const int* in_sizes, int n_in,
                              void* d_out, int out_size)
{
    (void)in_sizes; (void)n_in;
    const float* x     = (const float*)d_in[0];
    const float* convw = (const float*)d_in[1];
    const float* convb = (const float*)d_in[2];
    const float* lng   = (const float*)d_in[3];
    const float* lnb   = (const float*)d_in[4];
    const float* Wih   = (const float*)d_in[5];
    const float* Whh   = (const float*)d_in[6];
    const float* rr    = (const float*)d_in[7];
    const float* ss    = (const float*)d_in[8];
    const float* bb    = (const float*)d_in[9];

    float* out = (float*)d_out;
    size_t h_elems = (size_t)Bn * En * Ln * Hn;
    float* hlast = nullptr;
    if ((size_t)out_size >= h_elems + (size_t)Bn * En * Hn)
        hlast = out + h_elems;

    float *p_ln, *p_u, *p_y, *p_pre;
    cudaGetSymbolAddress((void**)&p_ln, g_ln);
    cudaGetSymbolAddress((void**)&p_u, g_u);
    cudaGetSymbolAddress((void**)&p_y, g_y);
    cudaGetSymbolAddress((void**)&p_pre, g_pre);

    ln_kernel<<<Bn * Ln, 256>>>(x, lng, lnb, p_ln);
    conv_kernel<<<(Bn * Ln * Dn) / 256, 256>>>(p_ln, convw, convb, p_u);

    for (int i = 0; i < NLn; i++) {
        const float* inx = (i == 0) ? p_u : p_y;
        gemm_kernel<<<dim3(MROWS / 128, Hn / 64), 256>>>(
            inx,
            Wih + (size_t)i * Hn * Dn,
            rr + (size_t)i * En * Dn,
            ss + (size_t)i * En * Hn,
            bb + (size_t)i * Hn,
            p_pre, (i == 0) ? 1 : 0);

        float* yo = (i == NLn - 1) ? out : p_y;
        rec_kernel<<<dim3(2, 64), 256>>>(
            p_pre,
            Whh + (size_t)i * Hn * Hn,
            yo,
            (i == NLn - 1) ? hlast : (float*)nullptr);
    }
}